// round 1
// baseline (speedup 1.0000x reference)
#include <cuda_runtime.h>
#include <cstddef>

// ---------------- problem constants ----------------
#define BATCH 2
#define CH    256
#define DD    8
#define HH    56
#define WW    56
#define SP    25088          // DD*HH*WW
#define T_TOK 50176          // BATCH*SP
#define NH    4
#define HD    64
#define NTOK  98             // 2*7*7 tokens per window
#define SCALE_Q 0.125f

// ---------------- scratch (device globals; no allocation allowed) ----------------
__device__ float g_xln [(size_t)T_TOK*256];
__device__ float g_qkv [(size_t)T_TOK*768];
__device__ float g_attn[(size_t)T_TOK*256];
__device__ float g_xw  [(size_t)T_TOK*256];
__device__ float g_y   [(size_t)T_TOK*256];
__device__ float g_s   [(size_t)T_TOK*256];   // s in NCDHW
__device__ float g_t   [(size_t)2*128*SP];    // conv temp
__device__ float g_wT  [128*128*27];          // transposed conv weights [ci][tap][co]

// ---------------- LN over channel dim, input NCDHW (fused transpose) ----------------
// block handles 28 consecutive w positions (one (b,d,h) row half); out token-major [t][256]
__global__ __launch_bounds__(256) void ln_in_kernel(
    const float* __restrict__ in, const float* __restrict__ w,
    const float* __restrict__ b, float* __restrict__ out)
{
    __shared__ float s[28][257];
    int bx = blockIdx.x;
    int wt  = bx & 1; int tmp = bx >> 1;
    int h   = tmp % 56; tmp /= 56;
    int d   = tmp & 7;  int bb = tmp >> 3;
    int w0  = wt * 28;
    size_t sp = ((size_t)d*56 + h)*56 + w0;
    const float* ib = in + (size_t)bb*256*SP + sp;
    for (int i = threadIdx.x; i < 28*256; i += 256) {
        int c = i / 28, ww_ = i - c*28;
        s[ww_][c] = ib[(size_t)c*SP + ww_];
    }
    __syncthreads();
    int warp = threadIdx.x >> 5, lane = threadIdx.x & 31;
    for (int tk = warp; tk < 28; tk += 8) {
        float s1 = 0.f, s2 = 0.f;
        #pragma unroll
        for (int j = 0; j < 8; j++) { float v = s[tk][lane + (j<<5)]; s1 += v; s2 += v*v; }
        #pragma unroll
        for (int o = 16; o; o >>= 1) {
            s1 += __shfl_xor_sync(0xffffffffu, s1, o);
            s2 += __shfl_xor_sync(0xffffffffu, s2, o);
        }
        float m  = s1 * (1.f/256.f);
        float var = s2 * (1.f/256.f) - m*m;
        float iv = rsqrtf(var + 1e-5f);
        size_t t = (size_t)bb*SP + sp + tk;
        float* orow = out + t*256;
        #pragma unroll
        for (int j = 0; j < 8; j++) {
            int c = lane + (j<<5);
            orow[c] = (s[tk][c] - m) * iv * w[c] + b[c];
        }
    }
}

// ---------------- LN over rows of a token-major [T,256] tensor ----------------
__global__ __launch_bounds__(256) void ln_row_kernel(
    const float* __restrict__ in, const float* __restrict__ w,
    const float* __restrict__ b, float* __restrict__ out)
{
    int t = blockIdx.x*8 + (threadIdx.x >> 5);
    int lane = threadIdx.x & 31;
    const float* row = in + (size_t)t*256;
    float v[8]; float s1 = 0.f, s2 = 0.f;
    #pragma unroll
    for (int j = 0; j < 8; j++) { v[j] = row[lane + (j<<5)]; s1 += v[j]; s2 += v[j]*v[j]; }
    #pragma unroll
    for (int o = 16; o; o >>= 1) {
        s1 += __shfl_xor_sync(0xffffffffu, s1, o);
        s2 += __shfl_xor_sync(0xffffffffu, s2, o);
    }
    float m  = s1 * (1.f/256.f);
    float var = s2 * (1.f/256.f) - m*m;
    float iv = rsqrtf(var + 1e-5f);
    float* orow = out + (size_t)t*256;
    #pragma unroll
    for (int j = 0; j < 8; j++) {
        int c = lane + (j<<5);
        orow[c] = (v[j] - m) * iv * w[c] + b[c];
    }
}

// ---------------- SGEMM: C[M,N] = A[M,K] @ B[N,K]^T  (+bias[N]) (+res[M,N]) ----------------
// BM=128 BN=64 BK=16, 256 threads, 8x4 per thread
__global__ __launch_bounds__(256) void gemm_tn_kernel(
    const float* __restrict__ A, const float* __restrict__ B,
    const float* __restrict__ bias, const float* __restrict__ res,
    float* __restrict__ C, int M, int N, int K)
{
    __shared__ float As[16][128];
    __shared__ float Bs[16][64];
    int bx = blockIdx.x, by = blockIdx.y;
    int tid = threadIdx.x;
    int ty = tid >> 4, tx = tid & 15;
    float4 acc[8];
    #pragma unroll
    for (int i = 0; i < 8; i++) acc[i] = make_float4(0.f,0.f,0.f,0.f);
    const int nK = K >> 4;
    for (int kb = 0; kb < nK; kb++) {
        #pragma unroll
        for (int l = 0; l < 2; l++) {
            int i = tid + (l<<8);
            int row = i >> 2, kq = (i & 3) << 2;
            float4 v = *(const float4*)(A + (size_t)(by*128 + row)*K + (kb<<4) + kq);
            As[kq+0][row]=v.x; As[kq+1][row]=v.y; As[kq+2][row]=v.z; As[kq+3][row]=v.w;
        }
        {
            int row = tid >> 2, kq = (tid & 3) << 2;
            float4 v = *(const float4*)(B + (size_t)(bx*64 + row)*K + (kb<<4) + kq);
            Bs[kq+0][row]=v.x; Bs[kq+1][row]=v.y; Bs[kq+2][row]=v.z; Bs[kq+3][row]=v.w;
        }
        __syncthreads();
        #pragma unroll
        for (int k = 0; k < 16; k++) {
            float4 a0 = *(const float4*)&As[k][ty<<3];
            float4 a1 = *(const float4*)&As[k][(ty<<3) + 4];
            float4 b0 = *(const float4*)&Bs[k][tx<<2];
            float a[8] = {a0.x,a0.y,a0.z,a0.w,a1.x,a1.y,a1.z,a1.w};
            #pragma unroll
            for (int i = 0; i < 8; i++) {
                acc[i].x += a[i]*b0.x; acc[i].y += a[i]*b0.y;
                acc[i].z += a[i]*b0.z; acc[i].w += a[i]*b0.w;
            }
        }
        __syncthreads();
    }
    float4 bv = make_float4(0.f,0.f,0.f,0.f);
    if (bias) bv = *(const float4*)(bias + (bx<<6) + (tx<<2));
    #pragma unroll
    for (int i = 0; i < 8; i++) {
        size_t m = (size_t)by*128 + (ty<<3) + i;
        size_t off = m*(size_t)N + (bx<<6) + (tx<<2);
        float4 v = acc[i];
        v.x += bv.x; v.y += bv.y; v.z += bv.z; v.w += bv.w;
        if (res) {
            float4 r = *(const float4*)(res + off);
            v.x += r.x; v.y += r.y; v.z += r.z; v.w += r.w;
        }
        *(float4*)(C + off) = v;
    }
}

// ---------------- windowed / grid attention ----------------
// one block per (window, head); 98 tokens, HD=64; smem: K[98][64], V[98][64], scores[98][98]
__global__ __launch_bounds__(128) void attn_kernel(
    const float* __restrict__ qkv, const float* __restrict__ btab,
    float* __restrict__ out, int grid_mode)
{
    extern __shared__ float sm[];
    float* ks = sm;
    float* vs = sm + NTOK*64;
    float* sc = sm + 2*NTOK*64;
    __shared__ int ts[NTOK];
    int wi = blockIdx.x, head = blockIdx.y;
    int b  = wi >> 8, wd = (wi>>6)&3, wh = (wi>>3)&7, ww = wi & 7;
    int tid = threadIdx.x;
    if (tid < NTOK) {
        int pd = tid / 49; int r7 = tid - pd*49; int ph = r7 / 7, pw = r7 - ph*7;
        int d, h, w;
        if (grid_mode) { d = pd*4 + wd; h = ph*8 + wh; w = pw*8 + ww; }
        else           { d = wd*2 + pd; h = wh*7 + ph; w = ww*7 + pw; }
        ts[tid] = ((b*8 + d)*56 + h)*56 + w;
    }
    __syncthreads();
    int hoff = head << 6;
    for (int i = tid; i < NTOK*64; i += 128) {
        int r = i >> 6, c = i & 63;
        size_t base = (size_t)ts[r]*768 + hoff + c;
        ks[i] = qkv[base + 256];
        vs[i] = qkv[base + 512];
    }
    __syncthreads();
    int r = tid;
    if (r < NTOK) {
        float4 q4[16];
        const float4* qp = (const float4*)(qkv + (size_t)ts[r]*768 + hoff);
        #pragma unroll
        for (int i = 0; i < 16; i++) {
            float4 v = qp[i];
            v.x *= SCALE_Q; v.y *= SCALE_Q; v.z *= SCALE_Q; v.w *= SCALE_Q;
            q4[i] = v;
        }
        int pd_r = r / 49; int rr = r - pd_r*49; int ph_r = rr/7, pw_r = rr - ph_r*7;
        float mx = -1e30f;
        for (int m = 0; m < NTOK; m++) {
            const float4* kk = (const float4*)(ks + (m<<6));
            float s0=0.f, s1=0.f, s2=0.f, s3=0.f;
            #pragma unroll
            for (int i = 0; i < 16; i += 4) {
                float4 k0 = kk[i+0];
                s0 += q4[i+0].x*k0.x + q4[i+0].y*k0.y + q4[i+0].z*k0.z + q4[i+0].w*k0.w;
                float4 k1 = kk[i+1];
                s1 += q4[i+1].x*k1.x + q4[i+1].y*k1.y + q4[i+1].z*k1.z + q4[i+1].w*k1.w;
                float4 k2 = kk[i+2];
                s2 += q4[i+2].x*k2.x + q4[i+2].y*k2.y + q4[i+2].z*k2.z + q4[i+2].w*k2.w;
                float4 k3 = kk[i+3];
                s3 += q4[i+3].x*k3.x + q4[i+3].y*k3.y + q4[i+3].z*k3.z + q4[i+3].w*k3.w;
            }
            int pd_m = m / 49; int mm = m - pd_m*49; int ph_m = mm/7, pw_m = mm - ph_m*7;
            int rpi = ((pd_r - pd_m + 1)*13 + (ph_r - ph_m + 6))*13 + (pw_r - pw_m + 6);
            float s = (s0+s1) + (s2+s3) + btab[(rpi<<2) + head];
            sc[r*NTOK + m] = s;
            mx = fmaxf(mx, s);
        }
        float sum = 0.f;
        for (int m = 0; m < NTOK; m++) {
            float e = __expf(sc[r*NTOK + m] - mx);
            sc[r*NTOK + m] = e; sum += e;
        }
        float inv = 1.f / sum;
        float4 a4[16];
        #pragma unroll
        for (int i = 0; i < 16; i++) a4[i] = make_float4(0.f,0.f,0.f,0.f);
        for (int m = 0; m < NTOK; m++) {
            float a = sc[r*NTOK + m] * inv;
            const float4* vv = (const float4*)(vs + (m<<6));
            #pragma unroll
            for (int i = 0; i < 16; i++) {
                float4 v = vv[i];
                a4[i].x += a*v.x; a4[i].y += a*v.y; a4[i].z += a*v.z; a4[i].w += a*v.w;
            }
        }
        float4* op = (float4*)(out + (size_t)ts[r]*256 + hoff);
        #pragma unroll
        for (int i = 0; i < 16; i++) op[i] = a4[i];
    }
}

// ---------------- s = input + y (token-major -> NCDHW) ----------------
__global__ __launch_bounds__(256) void add_s_kernel(
    const float* __restrict__ in, const float* __restrict__ y, float* __restrict__ s)
{
    __shared__ float sm[256][33];
    int b0 = blockIdx.x * 32;                    // 32 consecutive tokens, never straddles batch
    for (int i = threadIdx.x; i < 32*256; i += 256) {
        int tk = i >> 8, c = i & 255;
        sm[c][tk] = y[(size_t)(b0 + tk)*256 + c];
    }
    __syncthreads();
    int b = b0 / SP; int sp0 = b0 % SP;
    for (int i = threadIdx.x; i < 32*256; i += 256) {
        int c = i >> 5, k = i & 31;
        size_t gi = ((size_t)b*256 + c)*SP + sp0 + k;
        s[gi] = in[gi] + sm[c][k];
    }
}

// ---------------- conv weight transpose: [co][ci][tap] -> [ci][tap][co] ----------------
__global__ void wT_kernel(const float* __restrict__ w, float* __restrict__ o)
{
    int i = blockIdx.x*256 + threadIdx.x;
    if (i >= 128*128*27) return;
    int co = i & 127; int rest = i >> 7;         // rest = ci*27 + tap
    o[i] = w[co*3456 + rest];
}

// ---------------- direct 3x3x3 conv, 128->128ch, SAME; fused bias/leaky/residual --------
// block: 8x8 spatial tile (one d,b) x 32 output channels. 256 thr: 32 spatial-slots x 8 co-slots,
// each thread: 2 w positions x 4 co = 8 accumulators.
__global__ __launch_bounds__(256) void conv3d_kernel(
    const float* __restrict__ in, size_t in_bstride,
    const float* __restrict__ wT, const float* __restrict__ bias,
    const float* __restrict__ res, size_t res_bstride,
    float* __restrict__ out, size_t out_bstride, int leaky)
{
    __shared__ float sin_[3][10][10];
    __shared__ __align__(16) float sw[27][32];
    int bx = blockIdx.x;
    int wt = bx % 7; int ht = (bx/7) % 7; int d0 = (bx/49) & 7; int b = bx / 392;
    int cog = blockIdx.y;
    int h0 = ht*8, w0 = wt*8;
    int tid = threadIdx.x;
    int sp = tid & 31, cs = tid >> 5;
    int hy = sp >> 2, wx = (sp & 3) << 1;
    float acc[4][2] = {};
    const float* inb = in + (size_t)b*in_bstride;
    for (int ci = 0; ci < 128; ci++) {
        __syncthreads();
        for (int i = tid; i < 300; i += 256) {
            int dz = i/100; int rr = i - dz*100; int hh = rr/10; int w_ = rr - hh*10;
            int dd = d0 - 1 + dz, h = h0 - 1 + hh, w = w0 - 1 + w_;
            float v = 0.f;
            if (dd >= 0 && dd < 8 && (unsigned)h < 56u && (unsigned)w < 56u)
                v = inb[(size_t)ci*SP + (dd*56 + h)*56 + w];
            sin_[dz][hh][w_] = v;
        }
        for (int i = tid; i < 864; i += 256) {
            int tap = i >> 5, col = i & 31;
            sw[tap][col] = wT[(size_t)(ci*27 + tap)*128 + cog*32 + col];
        }
        __syncthreads();
        #pragma unroll
        for (int kd = 0; kd < 3; kd++)
        #pragma unroll
        for (int kh = 0; kh < 3; kh++)
        #pragma unroll
        for (int kw = 0; kw < 3; kw++) {
            float i0 = sin_[kd][hy+kh][wx+kw];
            float i1 = sin_[kd][hy+kh][wx+kw+1];
            int tap = (kd*3 + kh)*3 + kw;
            float4 wv = *(const float4*)&sw[tap][cs<<2];
            acc[0][0] += wv.x*i0; acc[0][1] += wv.x*i1;
            acc[1][0] += wv.y*i0; acc[1][1] += wv.y*i1;
            acc[2][0] += wv.z*i0; acc[2][1] += wv.z*i1;
            acc[3][0] += wv.w*i0; acc[3][1] += wv.w*i1;
        }
    }
    int h = h0 + hy;
    #pragma unroll
    for (int cl = 0; cl < 4; cl++) {
        int co = cog*32 + (cs<<2) + cl;
        float bb = bias[co];
        #pragma unroll
        for (int wi = 0; wi < 2; wi++) {
            int w = w0 + wx + wi;
            float v = acc[cl][wi] + bb;
            if (leaky) v = (v >= 0.f) ? v : 0.01f*v;
            size_t idx = (size_t)co*SP + ((size_t)d0*56 + h)*56 + w;
            if (res) v += res[(size_t)b*res_bstride + idx];
            out[(size_t)b*out_bstride + idx] = v;
        }
    }
}

// ---------------- launcher ----------------
extern "C" void kernel_launch(void* const* d_in, const int* in_sizes, int n_in,
                              void* d_out, int out_size)
{
    (void)in_sizes; (void)n_in; (void)out_size;
    const float* input  = (const float*)d_in[0];
    const float* n1w    = (const float*)d_in[1];
    const float* n1b    = (const float*)d_in[2];
    const float* n2w    = (const float*)d_in[3];
    const float* n2b    = (const float*)d_in[4];
    const float* wqkv   = (const float*)d_in[5];
    const float* wprojw = (const float*)d_in[6];
    const float* wprojb = (const float*)d_in[7];
    const float* wbias  = (const float*)d_in[8];
    const float* gqkv   = (const float*)d_in[9];
    const float* gprojw = (const float*)d_in[10];
    const float* gprojb = (const float*)d_in[11];
    const float* gbias  = (const float*)d_in[12];
    const float* f1c1w  = (const float*)d_in[13];
    const float* f1c1b  = (const float*)d_in[14];
    const float* f1c2w  = (const float*)d_in[15];
    const float* f1c2b  = (const float*)d_in[16];
    const float* g1c1w  = (const float*)d_in[17];
    const float* g1c1b  = (const float*)d_in[18];
    const float* g1c2w  = (const float*)d_in[19];
    const float* g1c2b  = (const float*)d_in[20];
    float* out = (float*)d_out;

    float *xln, *qkvb, *attn, *xw, *y, *s, *t, *wT;
    cudaGetSymbolAddress((void**)&xln,  g_xln);
    cudaGetSymbolAddress((void**)&qkvb, g_qkv);
    cudaGetSymbolAddress((void**)&attn, g_attn);
    cudaGetSymbolAddress((void**)&xw,   g_xw);
    cudaGetSymbolAddress((void**)&y,    g_y);
    cudaGetSymbolAddress((void**)&s,    g_s);
    cudaGetSymbolAddress((void**)&t,    g_t);
    cudaGetSymbolAddress((void**)&wT,   g_wT);

    const int ATTN_SMEM = (2*NTOK*64 + NTOK*NTOK) * (int)sizeof(float); // 88592 B
    cudaFuncSetAttribute(attn_kernel, cudaFuncAttributeMaxDynamicSharedMemorySize, ATTN_SMEM);

    // 1. LN1 (with NCDHW->token transpose)
    ln_in_kernel<<<1792, 256>>>(input, n1w, n1b, xln);
    // 2. window QKV
    gemm_tn_kernel<<<dim3(12, 392), 256>>>(xln, wqkv, nullptr, nullptr, qkvb, T_TOK, 768, 256);
    // 3. window attention
    attn_kernel<<<dim3(512, 4), 128, ATTN_SMEM>>>(qkvb, wbias, attn, 0);
    // 4. window proj -> xw
    gemm_tn_kernel<<<dim3(4, 392), 256>>>(attn, wprojw, wprojb, nullptr, xw, T_TOK, 256, 256);
    // 5. LN2
    ln_row_kernel<<<6272, 256>>>(xw, n2w, n2b, xln);
    // 6. grid QKV
    gemm_tn_kernel<<<dim3(12, 392), 256>>>(xln, gqkv, nullptr, nullptr, qkvb, T_TOK, 768, 256);
    // 7. grid attention
    attn_kernel<<<dim3(512, 4), 128, ATTN_SMEM>>>(qkvb, gbias, attn, 1);
    // 8. grid proj + residual xw -> y
    gemm_tn_kernel<<<dim3(4, 392), 256>>>(attn, gprojw, gprojb, xw, y, T_TOK, 256, 256);
    // 9. s = input + y (back to NCDHW)
    add_s_kernel<<<1568, 256>>>(input, y, s);

    // 10. t1 = leaky(conv(s2, f1c1) + b)
    wT_kernel<<<1728, 256>>>(f1c1w, wT);
    conv3d_kernel<<<dim3(784, 4), 256>>>(s + (size_t)128*SP, (size_t)256*SP,
                                         wT, f1c1b, nullptr, 0,
                                         t, (size_t)128*SP, 1);
    // 11. y1 = s1 + conv(t1, f1c2) + b  -> out channels [0,128)
    wT_kernel<<<1728, 256>>>(f1c2w, wT);
    conv3d_kernel<<<dim3(784, 4), 256>>>(t, (size_t)128*SP,
                                         wT, f1c2b, s, (size_t)256*SP,
                                         out, (size_t)256*SP, 0);
    // 12. t2 = leaky(conv(y1, g1c1) + b)
    wT_kernel<<<1728, 256>>>(g1c1w, wT);
    conv3d_kernel<<<dim3(784, 4), 256>>>(out, (size_t)256*SP,
                                         wT, g1c1b, nullptr, 0,
                                         t, (size_t)128*SP, 1);
    // 13. y2 = s2 + conv(t2, g1c2) + b  -> out channels [128,256)
    wT_kernel<<<1728, 256>>>(g1c2w, wT);
    conv3d_kernel<<<dim3(784, 4), 256>>>(t, (size_t)128*SP,
                                         wT, g1c2b, s + (size_t)128*SP, (size_t)256*SP,
                                         out + (size_t)128*SP, (size_t)256*SP, 0);
}

// round 3
// speedup vs baseline: 2.2793x; 2.2793x over previous
#include <cuda_runtime.h>
#include <cstdint>
#include <cstddef>

// ---------------- problem constants ----------------
#define SP    25088          // 8*56*56
#define T_TOK 50176          // 2*SP
#define NTOK  98
#define SCALE_Q 0.125f
#define PAD_SP 33640         // 10*58*58
#define PDH    3364          // 58*58

// ---------------- scratch ----------------
__device__ float g_xln [(size_t)T_TOK*256];
__device__ float g_qkv [(size_t)T_TOK*768];
__device__ float g_attn[(size_t)T_TOK*256];
__device__ float g_xw  [(size_t)T_TOK*256];
__device__ float g_y   [(size_t)T_TOK*256];
__device__ float g_s   [(size_t)T_TOK*256];
__device__ float g_Xa  [(size_t)2*PAD_SP*128];   // zero-init padding stays zero
__device__ float g_Xb  [(size_t)2*PAD_SP*128];
__device__ float g_w2  [27*128*128];             // [tap][co][ci]

// ---------------- PTX helpers (sm_80-baseline only!) ----------------
__device__ __forceinline__ uint32_t smem_u32(const void* p) {
    uint32_t a;
    asm("{ .reg .u64 t; cvta.to.shared.u64 t, %1; cvt.u32.u64 %0, t; }" : "=r"(a) : "l"(p));
    return a;
}
__device__ __forceinline__ void cp16(uint32_t s, const void* g) {
    asm volatile("cp.async.cg.shared.global [%0], [%1], 16;" :: "r"(s), "l"(g));
}
#define CP_COMMIT() asm volatile("cp.async.commit_group;" ::: "memory")
#define CP_WAIT1()  asm volatile("cp.async.wait_group 1;"  ::: "memory")

__device__ __forceinline__ float to_tf32(float x) {
    float r;
    asm("cvt.rna.tf32.f32 %0, %1;" : "=f"(r) : "f"(x));
    return r;
}

#define MMA_TF32(c, a, b0, b1) \
    asm volatile("mma.sync.aligned.m16n8k8.row.col.f32.tf32.tf32.f32 " \
        "{%0,%1,%2,%3}, {%4,%5,%6,%7}, {%8,%9}, {%0,%1,%2,%3};" \
        : "+f"((c)[0]), "+f"((c)[1]), "+f"((c)[2]), "+f"((c)[3]) \
        : "r"(__float_as_uint((a)[0])), "r"(__float_as_uint((a)[1])), \
          "r"(__float_as_uint((a)[2])), "r"(__float_as_uint((a)[3])), \
          "r"(__float_as_uint(b0)),   "r"(__float_as_uint(b1)))

// ---------------- LN kernels ----------------
__global__ __launch_bounds__(256) void ln_in_kernel(
    const float* __restrict__ in, const float* __restrict__ w,
    const float* __restrict__ b, float* __restrict__ out)
{
    __shared__ float s[28][257];
    int bx = blockIdx.x;
    int wt = bx & 1; int tmp = bx >> 1;
    int h = tmp % 56; tmp /= 56;
    int d = tmp & 7; int bb = tmp >> 3;
    int w0 = wt * 28;
    size_t sp = ((size_t)d*56 + h)*56 + w0;
    const float* ib = in + (size_t)bb*256*SP + sp;
    for (int i = threadIdx.x; i < 28*256; i += 256) {
        int c = i / 28, ww_ = i - c*28;
        s[ww_][c] = ib[(size_t)c*SP + ww_];
    }
    __syncthreads();
    int warp = threadIdx.x >> 5, lane = threadIdx.x & 31;
    for (int tk = warp; tk < 28; tk += 8) {
        float s1 = 0.f, s2 = 0.f;
        #pragma unroll
        for (int j = 0; j < 8; j++) { float v = s[tk][lane + (j<<5)]; s1 += v; s2 += v*v; }
        #pragma unroll
        for (int o = 16; o; o >>= 1) {
            s1 += __shfl_xor_sync(0xffffffffu, s1, o);
            s2 += __shfl_xor_sync(0xffffffffu, s2, o);
        }
        float m = s1 * (1.f/256.f);
        float var = s2 * (1.f/256.f) - m*m;
        float iv = rsqrtf(var + 1e-5f);
        size_t t = (size_t)bb*SP + sp + tk;
        float* orow = out + t*256;
        #pragma unroll
        for (int j = 0; j < 8; j++) {
            int c = lane + (j<<5);
            orow[c] = (s[tk][c] - m) * iv * w[c] + b[c];
        }
    }
}

__global__ __launch_bounds__(256) void ln_row_kernel(
    const float* __restrict__ in, const float* __restrict__ w,
    const float* __restrict__ b, float* __restrict__ out)
{
    int t = blockIdx.x*8 + (threadIdx.x >> 5);
    int lane = threadIdx.x & 31;
    const float* row = in + (size_t)t*256;
    float v[8]; float s1 = 0.f, s2 = 0.f;
    #pragma unroll
    for (int j = 0; j < 8; j++) { v[j] = row[lane + (j<<5)]; s1 += v[j]; s2 += v[j]*v[j]; }
    #pragma unroll
    for (int o = 16; o; o >>= 1) {
        s1 += __shfl_xor_sync(0xffffffffu, s1, o);
        s2 += __shfl_xor_sync(0xffffffffu, s2, o);
    }
    float m = s1 * (1.f/256.f);
    float var = s2 * (1.f/256.f) - m*m;
    float iv = rsqrtf(var + 1e-5f);
    float* orow = out + (size_t)t*256;
    #pragma unroll
    for (int j = 0; j < 8; j++) {
        int c = lane + (j<<5);
        orow[c] = (v[j] - m) * iv * w[c] + b[c];
    }
}

// ---------------- SGEMM (unchanged) ----------------
__global__ __launch_bounds__(256) void gemm_tn_kernel(
    const float* __restrict__ A, const float* __restrict__ B,
    const float* __restrict__ bias, const float* __restrict__ res,
    float* __restrict__ C, int M, int N, int K)
{
    __shared__ float As[16][128];
    __shared__ float Bs[16][64];
    int bx = blockIdx.x, by = blockIdx.y;
    int tid = threadIdx.x;
    int ty = tid >> 4, tx = tid & 15;
    float4 acc[8];
    #pragma unroll
    for (int i = 0; i < 8; i++) acc[i] = make_float4(0.f,0.f,0.f,0.f);
    const int nK = K >> 4;
    for (int kb = 0; kb < nK; kb++) {
        #pragma unroll
        for (int l = 0; l < 2; l++) {
            int i = tid + (l<<8);
            int row = i >> 2, kq = (i & 3) << 2;
            float4 v = *(const float4*)(A + (size_t)(by*128 + row)*K + (kb<<4) + kq);
            As[kq+0][row]=v.x; As[kq+1][row]=v.y; As[kq+2][row]=v.z; As[kq+3][row]=v.w;
        }
        {
            int row = tid >> 2, kq = (tid & 3) << 2;
            float4 v = *(const float4*)(B + (size_t)(bx*64 + row)*K + (kb<<4) + kq);
            Bs[kq+0][row]=v.x; Bs[kq+1][row]=v.y; Bs[kq+2][row]=v.z; Bs[kq+3][row]=v.w;
        }
        __syncthreads();
        #pragma unroll
        for (int k = 0; k < 16; k++) {
            float4 a0 = *(const float4*)&As[k][ty<<3];
            float4 a1 = *(const float4*)&As[k][(ty<<3) + 4];
            float4 b0 = *(const float4*)&Bs[k][tx<<2];
            float a[8] = {a0.x,a0.y,a0.z,a0.w,a1.x,a1.y,a1.z,a1.w};
            #pragma unroll
            for (int i = 0; i < 8; i++) {
                acc[i].x += a[i]*b0.x; acc[i].y += a[i]*b0.y;
                acc[i].z += a[i]*b0.z; acc[i].w += a[i]*b0.w;
            }
        }
        __syncthreads();
    }
    float4 bv = make_float4(0.f,0.f,0.f,0.f);
    if (bias) bv = *(const float4*)(bias + (bx<<6) + (tx<<2));
    #pragma unroll
    for (int i = 0; i < 8; i++) {
        size_t m = (size_t)by*128 + (ty<<3) + i;
        size_t off = m*(size_t)N + (bx<<6) + (tx<<2);
        float4 v = acc[i];
        v.x += bv.x; v.y += bv.y; v.z += bv.z; v.w += bv.w;
        if (res) {
            float4 r = *(const float4*)(res + off);
            v.x += r.x; v.y += r.y; v.z += r.z; v.w += r.w;
        }
        *(float4*)(C + off) = v;
    }
}

// ---------------- attention (unchanged) ----------------
__global__ __launch_bounds__(128) void attn_kernel(
    const float* __restrict__ qkv, const float* __restrict__ btab,
    float* __restrict__ out, int grid_mode)
{
    extern __shared__ float sm[];
    float* ks = sm;
    float* vs = sm + NTOK*64;
    float* sc = sm + 2*NTOK*64;
    __shared__ int ts[NTOK];
    int wi = blockIdx.x, head = blockIdx.y;
    int b = wi >> 8, wd = (wi>>6)&3, wh = (wi>>3)&7, ww = wi & 7;
    int tid = threadIdx.x;
    if (tid < NTOK) {
        int pd = tid / 49; int r7 = tid - pd*49; int ph = r7 / 7, pw = r7 - ph*7;
        int d, h, w;
        if (grid_mode) { d = pd*4 + wd; h = ph*8 + wh; w = pw*8 + ww; }
        else           { d = wd*2 + pd; h = wh*7 + ph; w = ww*7 + pw; }
        ts[tid] = ((b*8 + d)*56 + h)*56 + w;
    }
    __syncthreads();
    int hoff = head << 6;
    for (int i = tid; i < NTOK*64; i += 128) {
        int r = i >> 6, c = i & 63;
        size_t base = (size_t)ts[r]*768 + hoff + c;
        ks[i] = qkv[base + 256];
        vs[i] = qkv[base + 512];
    }
    __syncthreads();
    int r = tid;
    if (r < NTOK) {
        float4 q4[16];
        const float4* qp = (const float4*)(qkv + (size_t)ts[r]*768 + hoff);
        #pragma unroll
        for (int i = 0; i < 16; i++) {
            float4 v = qp[i];
            v.x *= SCALE_Q; v.y *= SCALE_Q; v.z *= SCALE_Q; v.w *= SCALE_Q;
            q4[i] = v;
        }
        int pd_r = r / 49; int rr = r - pd_r*49; int ph_r = rr/7, pw_r = rr - ph_r*7;
        float mx = -1e30f;
        for (int m = 0; m < NTOK; m++) {
            const float4* kk = (const float4*)(ks + (m<<6));
            float s0=0.f,s1=0.f,s2=0.f,s3=0.f;
            #pragma unroll
            for (int i = 0; i < 16; i += 4) {
                float4 k0 = kk[i+0];
                s0 += q4[i+0].x*k0.x + q4[i+0].y*k0.y + q4[i+0].z*k0.z + q4[i+0].w*k0.w;
                float4 k1 = kk[i+1];
                s1 += q4[i+1].x*k1.x + q4[i+1].y*k1.y + q4[i+1].z*k1.z + q4[i+1].w*k1.w;
                float4 k2 = kk[i+2];
                s2 += q4[i+2].x*k2.x + q4[i+2].y*k2.y + q4[i+2].z*k2.z + q4[i+2].w*k2.w;
                float4 k3 = kk[i+3];
                s3 += q4[i+3].x*k3.x + q4[i+3].y*k3.y + q4[i+3].z*k3.z + q4[i+3].w*k3.w;
            }
            int pd_m = m / 49; int mm = m - pd_m*49; int ph_m = mm/7, pw_m = mm - ph_m*7;
            int rpi = ((pd_r - pd_m + 1)*13 + (ph_r - ph_m + 6))*13 + (pw_r - pw_m + 6);
            float s = (s0+s1) + (s2+s3) + btab[(rpi<<2) + head];
            sc[r*NTOK + m] = s;
            mx = fmaxf(mx, s);
        }
        float sum = 0.f;
        for (int m = 0; m < NTOK; m++) {
            float e = __expf(sc[r*NTOK + m] - mx);
            sc[r*NTOK + m] = e; sum += e;
        }
        float inv = 1.f / sum;
        float4 a4[16];
        #pragma unroll
        for (int i = 0; i < 16; i++) a4[i] = make_float4(0.f,0.f,0.f,0.f);
        for (int m = 0; m < NTOK; m++) {
            float a = sc[r*NTOK + m] * inv;
            const float4* vv = (const float4*)(vs + (m<<6));
            #pragma unroll
            for (int i = 0; i < 16; i++) {
                float4 v = vv[i];
                a4[i].x += a*v.x; a4[i].y += a*v.y; a4[i].z += a*v.z; a4[i].w += a*v.w;
            }
        }
        float4* op = (float4*)(out + (size_t)ts[r]*256 + hoff);
        #pragma unroll
        for (int i = 0; i < 16; i++) op[i] = a4[i];
    }
}

// ---------------- s = input + y; also emit padded token-major s2 -> Xa (tf32) ---------
__global__ __launch_bounds__(256) void add_s_kernel(
    const float* __restrict__ in, const float* __restrict__ y,
    float* __restrict__ s, float* __restrict__ Xa)
{
    __shared__ float sm[256][33];
    int b0 = blockIdx.x * 32;
    for (int i = threadIdx.x; i < 32*256; i += 256) {
        int tk = i >> 8, c = i & 255;
        sm[c][tk] = y[(size_t)(b0 + tk)*256 + c];
    }
    __syncthreads();
    int b = b0 / SP; int sp0 = b0 % SP;
    for (int i = threadIdx.x; i < 32*256; i += 256) {
        int c = i >> 5, k = i & 31;
        size_t gi = ((size_t)b*256 + c)*SP + sp0 + k;
        float v = in[gi] + sm[c][k];
        s[gi] = v;
        sm[c][k] = v;
    }
    __syncthreads();
    for (int i = threadIdx.x; i < 32*128; i += 256) {
        int tok = i >> 7, ci = i & 127;
        int sp = sp0 + tok;
        int d = sp / 3136; int r = sp - d*3136; int h = r / 56, w = r - h*56;
        int pad = (d+1)*PDH + (h+1)*58 + (w+1);
        Xa[((size_t)b*PAD_SP + pad)*128 + ci] = to_tf32(sm[128+ci][tok]);
    }
}

// ---------------- conv weight transform: [co][ci][tap] -> [tap][co][ci] (tf32) --------
__global__ void wt2_kernel(const float* __restrict__ w, float* __restrict__ o)
{
    int i = blockIdx.x*256 + threadIdx.x;
    if (i >= 27*128*128) return;
    int ci = i & 127; int r = i >> 7; int co = r & 127; int tap = r >> 7;
    o[i] = to_tf32(w[(co*128 + ci)*27 + tap]);
}

// ---------------- tf32 mma.sync implicit-GEMM conv ----------------
// block: M=128 positions x N=128 co; K = 27 taps x 128 ci staged in 108 chunks of 32.
// 8 warps = 4(M) x 2(N); warp tile 32x64 via m16n8k8; cp.async double buffer.
__global__ __launch_bounds__(256) void conv_mma_kernel(
    const float* __restrict__ Xin, const float* __restrict__ w2,
    const float* __restrict__ bias, const float* __restrict__ res,
    float* __restrict__ outN, float* __restrict__ outX, int leaky)
{
    extern __shared__ __align__(16) float dsm[];   // 2 stages x 8192 floats; epilogue Cbuf 128x132
    __shared__ float sbias[128];

    const int tid  = threadIdx.x;
    const int lane = tid & 31;
    const int wid  = tid >> 5;
    const int wm   = wid & 3;          // M tile (x32)
    const int wn   = wid >> 2;         // N tile (x64)
    const int r0   = lane >> 2;
    const int c0   = lane & 3;
    const int bx   = blockIdx.x;
    const int b    = bx / 196;
    const int spb  = (bx % 196) * 128;

    if (tid < 128) sbias[tid] = bias[tid];

    // staging assignment: thread copies row mrow, quads [q0, q0+4)
    const int mrow = tid >> 1;
    const int q0   = (tid & 1) * 4;
    int sp_c = spb + mrow;
    int d_c = sp_c / 3136; int r_c = sp_c - d_c*3136; int h_c = r_c / 56, w_c = r_c - h_c*56;
    const int padrow = d_c*PDH + h_c*58 + w_c;
    const float* XinB = Xin + (size_t)b * PAD_SP * 128;
    const uint32_t smem_base = smem_u32(dsm);
    const uint32_t arow = smem_base + (uint32_t)mrow*128u;

    float c[2][8][4];
    #pragma unroll
    for (int t = 0; t < 2; t++)
        #pragma unroll
        for (int t2 = 0; t2 < 8; t2++)
            #pragma unroll
            for (int j = 0; j < 4; j++) c[t][t2][j] = 0.f;

    const int NIT = 108;

    // stage loader
    auto load_stage = [&](int k) {
        int tap = k >> 2, kq = k & 3;
        int kd = tap / 9; int rem = tap - kd*9; int kh = rem / 3, kw = rem - kh*3;
        int toff = kd*PDH + kh*58 + kw;
        uint32_t sA = arow + (uint32_t)(k & 1) * 32768u;
        uint32_t sB = sA + 16384u;
        const float* ga = XinB + (size_t)(padrow + toff)*128 + kq*32;
        const float* gb = w2 + ((size_t)tap*128 + mrow)*128 + kq*32;
        #pragma unroll
        for (int q = q0; q < q0 + 4; q++) {
            uint32_t pq = (uint32_t)(q ^ (mrow & 7)) * 16u;
            cp16(sA + pq, ga + q*4);
            cp16(sB + pq, gb + q*4);
        }
    };

    load_stage(0);
    CP_COMMIT();

    for (int k = 0; k < NIT; k++) {
        if (k + 1 < NIT) load_stage(k + 1);
        CP_COMMIT();
        CP_WAIT1();
        __syncthreads();

        const float* As = dsm + (k & 1) * 8192;
        const float* Bs = As + 4096;
        #pragma unroll
        for (int kk = 0; kk < 4; kk++) {
            int k1 = kk*8 + c0, k2 = k1 + 4;
            float a[2][4];
            #pragma unroll
            for (int t = 0; t < 2; t++) {
                int rm  = wm*32 + t*16 + r0;     // rm&7 == r0
                int xm  = r0 << 2;
                a[t][0] = As[rm*32       + (k1 ^ xm)];
                a[t][1] = As[(rm+8)*32   + (k1 ^ xm)];
                a[t][2] = As[rm*32       + (k2 ^ xm)];
                a[t][3] = As[(rm+8)*32   + (k2 ^ xm)];
            }
            #pragma unroll
            for (int t2 = 0; t2 < 8; t2++) {
                int n  = wn*64 + t2*8 + r0;      // n&7 == r0
                int xn = r0 << 2;
                float b0 = Bs[n*32 + (k1 ^ xn)];
                float b1 = Bs[n*32 + (k2 ^ xn)];
                MMA_TF32(c[0][t2], a[0], b0, b1);
                MMA_TF32(c[1][t2], a[1], b0, b1);
            }
        }
        __syncthreads();
    }

    // ---------------- epilogue ----------------
    float* Cb = dsm;                               // 128 x 132
    #pragma unroll
    for (int t = 0; t < 2; t++) {
        int row = wm*32 + t*16 + r0;
        #pragma unroll
        for (int t2 = 0; t2 < 8; t2++) {
            int col = wn*64 + t2*8 + (c0 << 1);
            float b0s = sbias[col], b1s = sbias[col+1];
            float v0 = c[t][t2][0] + b0s;
            float v1 = c[t][t2][1] + b1s;
            float v2 = c[t][t2][2] + b0s;
            float v3 = c[t][t2][3] + b1s;
            if (leaky) {
                v0 = (v0 >= 0.f) ? v0 : 0.01f*v0;
                v1 = (v1 >= 0.f) ? v1 : 0.01f*v1;
                v2 = (v2 >= 0.f) ? v2 : 0.01f*v2;
                v3 = (v3 >= 0.f) ? v3 : 0.01f*v3;
            }
            Cb[row*132 + col]       = v0;
            Cb[row*132 + col + 1]   = v1;
            Cb[(row+8)*132 + col]   = v2;
            Cb[(row+8)*132 + col+1] = v3;
        }
    }
    __syncthreads();

    if (res) {
        int co = tid >> 1, mh = (tid & 1) << 6;
        const float* rp = res + (size_t)b*256*SP + (size_t)co*SP + spb + mh;
        #pragma unroll
        for (int j4 = 0; j4 < 16; j4++) {
            float4 r4 = *(const float4*)(rp + j4*4);
            Cb[(mh + j4*4 + 0)*132 + co] += r4.x;
            Cb[(mh + j4*4 + 1)*132 + co] += r4.y;
            Cb[(mh + j4*4 + 2)*132 + co] += r4.z;
            Cb[(mh + j4*4 + 3)*132 + co] += r4.w;
        }
        __syncthreads();
    }

    if (outX) {
        int m = tid >> 1, ch = (tid & 1) << 6;
        int sp = spb + m; int d = sp / 3136; int r = sp - d*3136; int h = r / 56, w = r - h*56;
        size_t po = (size_t)(d+1)*PDH + (size_t)(h+1)*58 + (w+1);
        float* xp = outX + ((size_t)b*PAD_SP + po)*128 + ch;
        #pragma unroll
        for (int j4 = 0; j4 < 16; j4++) {
            float4 v = *(const float4*)&Cb[m*132 + ch + j4*4];
            v.x = to_tf32(v.x); v.y = to_tf32(v.y); v.z = to_tf32(v.z); v.w = to_tf32(v.w);
            *(float4*)(xp + j4*4) = v;
        }
    }
    if (outN) {
        int co = tid >> 1, mh = (tid & 1) << 6;
        float* op = outN + (size_t)b*256*SP + (size_t)co*SP + spb + mh;
        #pragma unroll
        for (int j4 = 0; j4 < 16; j4++) {
            float4 o;
            o.x = Cb[(mh + j4*4 + 0)*132 + co];
            o.y = Cb[(mh + j4*4 + 1)*132 + co];
            o.z = Cb[(mh + j4*4 + 2)*132 + co];
            o.w = Cb[(mh + j4*4 + 3)*132 + co];
            *(float4*)(op + j4*4) = o;
        }
    }
}

// ---------------- launcher ----------------
extern "C" void kernel_launch(void* const* d_in, const int* in_sizes, int n_in,
                              void* d_out, int out_size)
{
    (void)in_sizes; (void)n_in; (void)out_size;
    const float* input  = (const float*)d_in[0];
    const float* n1w    = (const float*)d_in[1];
    const float* n1b    = (const float*)d_in[2];
    const float* n2w    = (const float*)d_in[3];
    const float* n2b    = (const float*)d_in[4];
    const float* wqkv   = (const float*)d_in[5];
    const float* wprojw = (const float*)d_in[6];
    const float* wprojb = (const float*)d_in[7];
    const float* wbias  = (const float*)d_in[8];
    const float* gqkv   = (const float*)d_in[9];
    const float* gprojw = (const float*)d_in[10];
    const float* gprojb = (const float*)d_in[11];
    const float* gbias  = (const float*)d_in[12];
    const float* f1c1w  = (const float*)d_in[13];
    const float* f1c1b  = (const float*)d_in[14];
    const float* f1c2w  = (const float*)d_in[15];
    const float* f1c2b  = (const float*)d_in[16];
    const float* g1c1w  = (const float*)d_in[17];
    const float* g1c1b  = (const float*)d_in[18];
    const float* g1c2w  = (const float*)d_in[19];
    const float* g1c2b  = (const float*)d_in[20];
    float* out = (float*)d_out;

    float *xln, *qkvb, *attn, *xw, *y, *s, *Xa, *Xb, *w2;
    cudaGetSymbolAddress((void**)&xln,  g_xln);
    cudaGetSymbolAddress((void**)&qkvb, g_qkv);
    cudaGetSymbolAddress((void**)&attn, g_attn);
    cudaGetSymbolAddress((void**)&xw,   g_xw);
    cudaGetSymbolAddress((void**)&y,    g_y);
    cudaGetSymbolAddress((void**)&s,    g_s);
    cudaGetSymbolAddress((void**)&Xa,   g_Xa);
    cudaGetSymbolAddress((void**)&Xb,   g_Xb);
    cudaGetSymbolAddress((void**)&w2,   g_w2);

    const int ATTN_SMEM = (2*NTOK*64 + NTOK*NTOK) * (int)sizeof(float);
    cudaFuncSetAttribute(attn_kernel, cudaFuncAttributeMaxDynamicSharedMemorySize, ATTN_SMEM);
    const int CONV_SMEM = 128*132*4;   // 67584 B (>= 2*32768 stage bytes)
    cudaFuncSetAttribute(conv_mma_kernel, cudaFuncAttributeMaxDynamicSharedMemorySize, CONV_SMEM);

    ln_in_kernel<<<1792, 256>>>(input, n1w, n1b, xln);
    gemm_tn_kernel<<<dim3(12, 392), 256>>>(xln, wqkv, nullptr, nullptr, qkvb, T_TOK, 768, 256);
    attn_kernel<<<dim3(512, 4), 128, ATTN_SMEM>>>(qkvb, wbias, attn, 0);
    gemm_tn_kernel<<<dim3(4, 392), 256>>>(attn, wprojw, wprojb, nullptr, xw, T_TOK, 256, 256);
    ln_row_kernel<<<6272, 256>>>(xw, n2w, n2b, xln);
    gemm_tn_kernel<<<dim3(12, 392), 256>>>(xln, gqkv, nullptr, nullptr, qkvb, T_TOK, 768, 256);
    attn_kernel<<<dim3(512, 4), 128, ATTN_SMEM>>>(qkvb, gbias, attn, 1);
    gemm_tn_kernel<<<dim3(4, 392), 256>>>(attn, gprojw, gprojb, xw, y, T_TOK, 256, 256);
    add_s_kernel<<<1568, 256>>>(input, y, s, Xa);

    // conv1: t1 = leaky(conv(s2, f1c1)+b)       Xa -> Xb
    wt2_kernel<<<1728, 256>>>(f1c1w, w2);
    conv_mma_kernel<<<392, 256, CONV_SMEM>>>(Xa, w2, f1c1b, nullptr, nullptr, Xb, 1);
    // conv2: y1 = s1 + conv(t1, f1c2)+b         Xb -> out[0:128] + Xa
    wt2_kernel<<<1728, 256>>>(f1c2w, w2);
    conv_mma_kernel<<<392, 256, CONV_SMEM>>>(Xb, w2, f1c2b, s, out, Xa, 0);
    // conv3: t2 = leaky(conv(y1, g1c1)+b)       Xa -> Xb
    wt2_kernel<<<1728, 256>>>(g1c1w, w2);
    conv_mma_kernel<<<392, 256, CONV_SMEM>>>(Xa, w2, g1c1b, nullptr, nullptr, Xb, 1);
    // conv4: y2 = s2 + conv(t2, g1c2)+b         Xb -> out[128:256]
    wt2_kernel<<<1728, 256>>>(g1c2w, w2);
    conv_mma_kernel<<<392, 256, CONV_SMEM>>>(Xb, w2, g1c2b, s + (size_t)128*SP,
                                             out + (size_t)128*SP, nullptr, 0);
}